// round 7
// baseline (speedup 1.0000x reference)
#include <cuda_runtime.h>
#include <cuda_bf16.h>
#include <cstdint>

// out = RowLocalAttn(v@Wq, v@Wk, v@Wv) @ Wp + bp
// v: [65536, 256] fp32. GEMMs: warp mma.sync bf16, 3-pass hi/lo split, fp32 accum.
// R7: fp32->split conversion fused into QKV GEMM A-path (split_kernel removed);
// attention k|v staged via cp.async with q loads overlapped.

#define M_TOTAL 65536
#define DIM     256

// ---------------- scratch ----------------------------------------------------
__device__ __align__(128) float          g_qkv[(size_t)M_TOTAL * 3 * DIM]; // [M][768]
__device__ __align__(128) unsigned short g_xhi[(size_t)M_TOTAL * DIM];
__device__ __align__(128) unsigned short g_xlo[(size_t)M_TOTAL * DIM];
__device__ __align__(128) unsigned short g_wqkv[2 * 768 * 256];  // hi plane, lo plane ([n][k])
__device__ __align__(128) unsigned short g_wp[2 * 256 * 256];

// ---------------- PTX helpers ------------------------------------------------
__device__ __forceinline__ uint32_t smem_u32(const void* p) {
    uint32_t a;
    asm("{ .reg .u64 t; cvta.to.shared.u64 t, %1; cvt.u32.u64 %0, t; }" : "=r"(a) : "l"(p));
    return a;
}
__device__ __forceinline__ void cp_async16(uint32_t s, const void* g) {
    asm volatile("cp.async.cg.shared.global [%0], [%1], 16;" :: "r"(s), "l"(g));
}
__device__ __forceinline__ void cp_commit() { asm volatile("cp.async.commit_group;"); }
template<int N>
__device__ __forceinline__ void cp_wait() { asm volatile("cp.async.wait_group %0;" :: "n"(N)); }
__device__ __forceinline__ void ldsm4(uint32_t* r, uint32_t a) {
    asm volatile("ldmatrix.sync.aligned.m8n8.x4.shared.b16 {%0,%1,%2,%3}, [%4];"
        : "=r"(r[0]), "=r"(r[1]), "=r"(r[2]), "=r"(r[3]) : "r"(a));
}
__device__ __forceinline__ void mma16816(float* d, const uint32_t* a, const uint32_t* b) {
    asm volatile("mma.sync.aligned.m16n8k16.row.col.f32.bf16.bf16.f32 "
        "{%0,%1,%2,%3}, {%4,%5,%6,%7}, {%8,%9}, {%0,%1,%2,%3};"
        : "+f"(d[0]), "+f"(d[1]), "+f"(d[2]), "+f"(d[3])
        : "r"(a[0]), "r"(a[1]), "r"(a[2]), "r"(a[3]), "r"(b[0]), "r"(b[1]));
}
// swizzled offset in an N-row x 64-byte tile (16B granules)
__device__ __forceinline__ uint32_t swz(int row, int c) {
    return (uint32_t)(row * 64 + ((c ^ ((row >> 1) & 3)) << 4));
}
// split 8 fp32 -> 8 bf16 hi (16B) + 8 bf16 lo (16B)
__device__ __forceinline__ void split8(const float4& f0, const float4& f1,
                                       uint4& hi, uint4& lo)
{
    float f[8] = {f0.x, f0.y, f0.z, f0.w, f1.x, f1.y, f1.z, f1.w};
    unsigned short hs[8], ls[8];
    #pragma unroll
    for (int i = 0; i < 8; i++) {
        __nv_bfloat16 h = __float2bfloat16(f[i]);
        __nv_bfloat16 l = __float2bfloat16(f[i] - __bfloat162float(h));
        hs[i] = *(unsigned short*)&h;
        ls[i] = *(unsigned short*)&l;
    }
    hi = *(uint4*)hs;
    lo = *(uint4*)ls;
}

// ---------------- weight conversion ------------------------------------------
__global__ __launch_bounds__(256)
void wconv_kernel(const float* __restrict__ Wq, const float* __restrict__ Wk,
                  const float* __restrict__ Wv, const float* __restrict__ Wp,
                  unsigned short* __restrict__ wqkv, unsigned short* __restrict__ wp)
{
    int wi = blockIdx.y;
    int n  = blockIdx.x;
    int k  = threadIdx.x;
    const float* W = (wi == 0) ? Wq : (wi == 1) ? Wk : (wi == 2) ? Wv : Wp;
    float val = W[k * 256 + n];
    __nv_bfloat16 h = __float2bfloat16(val);
    __nv_bfloat16 l = __float2bfloat16(val - __bfloat162float(h));
    if (wi < 3) {
        wqkv[(size_t)(wi * 256 + n) * 256 + k]                     = *(unsigned short*)&h;
        wqkv[(size_t)768 * 256 + (size_t)(wi * 256 + n) * 256 + k] = *(unsigned short*)&l;
    } else {
        wp[(size_t)n * 256 + k]                     = *(unsigned short*)&h;
        wp[(size_t)256 * 256 + (size_t)n * 256 + k] = *(unsigned short*)&l;
    }
}

// ---------------- QKV GEMM: fp32 A converted in-kernel ----------------------
// C[by*128..+128][bx*128..+128] = A @ B^T.  A fp32 [M][256], B hi/lo [768][256].
// A: LDG reg-prefetch + convert + STS, double buffered (2 x 16KB).
// B: cp.async 3-stage (3 x 16KB). Total smem 80KB.
static constexpr int FA_STRIDE = 16384;           // Ah 8K | Al 8K
static constexpr int FB_BASE   = 32768;
static constexpr int FB_STRIDE = 16384;           // Bh 8K | Bl 8K
static constexpr int GEMM3F_SMEM = FB_BASE + 3 * FB_STRIDE;  // 81920

__global__ __launch_bounds__(256)
void gemm3f_kernel(const float* __restrict__ A,
                   const unsigned short* __restrict__ Bhi, const unsigned short* __restrict__ Blo,
                   float* __restrict__ C, int ldc)
{
    extern __shared__ char smem[];
    const uint32_t sb = smem_u32(smem);
    const int tid  = threadIdx.x;
    const int wid  = tid >> 5;
    const int lane = tid & 31;
    const int mw = wid & 1;        // 2 warp rows (64 each)
    const int nw = wid >> 1;       // 4 warp cols (32 each)

    const int mbase = blockIdx.y * 128;
    const int nbase = blockIdx.x * 128;

    // per-thread A assignment: 2 x (row, kseg of 8)
    int arow[2], akseg[2];
    #pragma unroll
    for (int i = 0; i < 2; i++) {
        int a = tid + 256 * i;
        arow[i] = a >> 2;
        akseg[i] = a & 3;
    }

    float4 areg[2][2];
    auto ldgA = [&](int kc) {
        #pragma unroll
        for (int i = 0; i < 2; i++) {
            const float4* p = (const float4*)(A + (size_t)(mbase + arow[i]) * 256 + kc * 32 + akseg[i] * 8);
            areg[i][0] = p[0];
            areg[i][1] = p[1];
        }
    };
    auto stsA = [&](int buf) {
        const uint32_t base = sb + buf * FA_STRIDE;
        #pragma unroll
        for (int i = 0; i < 2; i++) {
            uint4 hi, lo;
            split8(areg[i][0], areg[i][1], hi, lo);
            uint32_t off = swz(arow[i], akseg[i]);
            *(uint4*)(smem + buf * FA_STRIDE + off)        = hi;
            *(uint4*)(smem + buf * FA_STRIDE + 8192 + off) = lo;
        }
        (void)base;
    };
    auto loadB = [&](int kc, int s) {
        const uint32_t stg = sb + FB_BASE + s * FB_STRIDE;
        #pragma unroll
        for (int i = 0; i < 2; i++) {
            int u = tid + i * 256;             // 512 granules per 8K tile
            int row = u >> 2, c = u & 3;
            uint32_t so = swz(row, c);
            size_t gb = (size_t)(nbase + row) * 256 + kc * 32 + c * 8;
            cp_async16(stg + so, Bhi + gb);
            cp_async16(stg + 8192 + so, Blo + gb);
        }
        cp_commit();
    };

    float acc[4][4][4];
    #pragma unroll
    for (int i = 0; i < 4; i++)
        #pragma unroll
        for (int j = 0; j < 4; j++)
            #pragma unroll
            for (int r = 0; r < 4; r++) acc[i][j][r] = 0.0f;

    // prologue
    ldgA(0);
    loadB(0, 0);
    loadB(1, 1);
    stsA(0);
    ldgA(1);

    for (int kc = 0; kc < 8; kc++) {
        if (kc == 7) cp_wait<0>(); else cp_wait<1>();
        __syncthreads();
        if (kc < 7) stsA((kc + 1) & 1);
        if (kc < 6) { ldgA(kc + 2); loadB(kc + 2, (kc + 2) % 3); }

        const uint32_t astg = sb + (kc & 1) * FA_STRIDE;
        const uint32_t bstg = sb + FB_BASE + (kc % 3) * FB_STRIDE;
        #pragma unroll
        for (int ks = 0; ks < 2; ks++) {
            uint32_t a_hi[4][4], a_lo[4][4];
            {
                int ar = mw * 64 + (lane & 15);
                int ac = ks * 2 + (lane >> 4);
                uint32_t base_off = swz(ar, ac);
                #pragma unroll
                for (int mt = 0; mt < 4; mt++) {
                    uint32_t off = base_off + mt * 16 * 64;
                    ldsm4(a_hi[mt], astg + off);
                    ldsm4(a_lo[mt], astg + 8192 + off);
                }
            }
            uint32_t b_hi[4][2], b_lo[4][2];
            {
                int nr0 = nw * 32 + ((lane >> 4) << 3) + (lane & 7);
                int bc  = ks * 2 + ((lane >> 3) & 1);
                #pragma unroll
                for (int nh = 0; nh < 2; nh++) {
                    uint32_t off = swz(nr0 + nh * 16, bc);
                    uint32_t r[4];
                    ldsm4(r, bstg + off);
                    b_hi[nh * 2][0] = r[0]; b_hi[nh * 2][1] = r[1];
                    b_hi[nh * 2 + 1][0] = r[2]; b_hi[nh * 2 + 1][1] = r[3];
                    ldsm4(r, bstg + 8192 + off);
                    b_lo[nh * 2][0] = r[0]; b_lo[nh * 2][1] = r[1];
                    b_lo[nh * 2 + 1][0] = r[2]; b_lo[nh * 2 + 1][1] = r[3];
                }
            }
            #pragma unroll
            for (int mt = 0; mt < 4; mt++)
                #pragma unroll
                for (int nt = 0; nt < 4; nt++)
                    mma16816(acc[mt][nt], a_hi[mt], b_hi[nt]);
            #pragma unroll
            for (int mt = 0; mt < 4; mt++)
                #pragma unroll
                for (int nt = 0; nt < 4; nt++)
                    mma16816(acc[mt][nt], a_hi[mt], b_lo[nt]);
            #pragma unroll
            for (int mt = 0; mt < 4; mt++)
                #pragma unroll
                for (int nt = 0; nt < 4; nt++)
                    mma16816(acc[mt][nt], a_lo[mt], b_hi[nt]);
        }
    }

    #pragma unroll
    for (int mt = 0; mt < 4; mt++) {
        int r0 = mbase + mw * 64 + mt * 16 + (lane >> 2);
        #pragma unroll
        for (int nt = 0; nt < 4; nt++) {
            int col = nbase + nw * 32 + nt * 8 + (lane & 3) * 2;
            *(float2*)(C + (size_t)r0 * ldc + col) = make_float2(acc[mt][nt][0], acc[mt][nt][1]);
            *(float2*)(C + (size_t)(r0 + 8) * ldc + col) = make_float2(acc[mt][nt][2], acc[mt][nt][3]);
        }
    }
}

// ---------------- final GEMM: split bf16 A (x), 3-stage cp.async -------------
static constexpr int STAGE_BYTES = 32768;
static constexpr int OFF_AH = 0, OFF_AL = 8192, OFF_BH = 16384, OFF_BL = 24576;
static constexpr int GEMM_SMEM = 3 * STAGE_BYTES;

__global__ __launch_bounds__(256)
void gemm3_kernel(const unsigned short* __restrict__ Ahi, const unsigned short* __restrict__ Alo,
                  const unsigned short* __restrict__ Bhi, const unsigned short* __restrict__ Blo,
                  const float* __restrict__ bias, float* __restrict__ C, int ldc)
{
    extern __shared__ char smem[];
    const uint32_t sb = smem_u32(smem);
    const int tid  = threadIdx.x;
    const int wid  = tid >> 5;
    const int lane = tid & 31;
    const int mw = wid & 1;
    const int nw = wid >> 1;

    const int mbase = blockIdx.y * 128;
    const int nbase = blockIdx.x * 128;

    auto load_chunk = [&](int kc, int s) {
        const uint32_t stg = sb + s * STAGE_BYTES;
        #pragma unroll
        for (int i = 0; i < 2; i++) {
            int u = tid + i * 256;
            int row = u >> 2, c = u & 3;
            uint32_t so = swz(row, c);
            size_t ga = (size_t)(mbase + row) * 256 + kc * 32 + c * 8;
            size_t gb = (size_t)(nbase + row) * 256 + kc * 32 + c * 8;
            cp_async16(stg + OFF_AH + so, Ahi + ga);
            cp_async16(stg + OFF_AL + so, Alo + ga);
            cp_async16(stg + OFF_BH + so, Bhi + gb);
            cp_async16(stg + OFF_BL + so, Blo + gb);
        }
        cp_commit();
    };

    float acc[4][4][4];
    #pragma unroll
    for (int i = 0; i < 4; i++)
        #pragma unroll
        for (int j = 0; j < 4; j++)
            #pragma unroll
            for (int r = 0; r < 4; r++) acc[i][j][r] = 0.0f;

    load_chunk(0, 0);
    load_chunk(1, 1);

    for (int kc = 0; kc < 8; kc++) {
        if (kc == 7) cp_wait<0>(); else cp_wait<1>();
        __syncthreads();
        if (kc < 6) load_chunk(kc + 2, (kc + 2) % 3);

        const uint32_t stg = sb + (kc % 3) * STAGE_BYTES;
        #pragma unroll
        for (int ks = 0; ks < 2; ks++) {
            uint32_t a_hi[4][4], a_lo[4][4];
            {
                int ar = mw * 64 + (lane & 15);
                int ac = ks * 2 + (lane >> 4);
                uint32_t base_off = swz(ar, ac);
                #pragma unroll
                for (int mt = 0; mt < 4; mt++) {
                    uint32_t off = base_off + mt * 16 * 64;
                    ldsm4(a_hi[mt], stg + OFF_AH + off);
                    ldsm4(a_lo[mt], stg + OFF_AL + off);
                }
            }
            uint32_t b_hi[4][2], b_lo[4][2];
            {
                int nr0 = nw * 32 + ((lane >> 4) << 3) + (lane & 7);
                int bc  = ks * 2 + ((lane >> 3) & 1);
                #pragma unroll
                for (int nh = 0; nh < 2; nh++) {
                    uint32_t off = swz(nr0 + nh * 16, bc);
                    uint32_t r[4];
                    ldsm4(r, stg + OFF_BH + off);
                    b_hi[nh * 2][0] = r[0]; b_hi[nh * 2][1] = r[1];
                    b_hi[nh * 2 + 1][0] = r[2]; b_hi[nh * 2 + 1][1] = r[3];
                    ldsm4(r, stg + OFF_BL + off);
                    b_lo[nh * 2][0] = r[0]; b_lo[nh * 2][1] = r[1];
                    b_lo[nh * 2 + 1][0] = r[2]; b_lo[nh * 2 + 1][1] = r[3];
                }
            }
            #pragma unroll
            for (int mt = 0; mt < 4; mt++)
                #pragma unroll
                for (int nt = 0; nt < 4; nt++)
                    mma16816(acc[mt][nt], a_hi[mt], b_hi[nt]);
            #pragma unroll
            for (int mt = 0; mt < 4; mt++)
                #pragma unroll
                for (int nt = 0; nt < 4; nt++)
                    mma16816(acc[mt][nt], a_hi[mt], b_lo[nt]);
            #pragma unroll
            for (int mt = 0; mt < 4; mt++)
                #pragma unroll
                for (int nt = 0; nt < 4; nt++)
                    mma16816(acc[mt][nt], a_lo[mt], b_hi[nt]);
        }
    }

    #pragma unroll
    for (int mt = 0; mt < 4; mt++) {
        int r0 = mbase + mw * 64 + mt * 16 + (lane >> 2);
        #pragma unroll
        for (int nt = 0; nt < 4; nt++) {
            int col = nbase + nw * 32 + nt * 8 + (lane & 3) * 2;
            float b0 = bias[col], b1 = bias[col + 1];
            *(float2*)(C + (size_t)r0 * ldc + col) =
                make_float2(acc[mt][nt][0] + b0, acc[mt][nt][1] + b1);
            *(float2*)(C + (size_t)(r0 + 8) * ldc + col) =
                make_float2(acc[mt][nt][2] + b0, acc[mt][nt][3] + b1);
        }
    }
}

// ---------------- row-local attention ----------------------------------------
// 32 rows/CTA, 256 threads = (row r = tid/8, head h = tid%8).
// k|v staged via cp.async (padded stride 516); q LDGs overlapped with staging.
#define KVSTR 516
__global__ __launch_bounds__(256, 3)
void attn_kernel(const float* __restrict__ qkv,
                 unsigned short* __restrict__ xhi, unsigned short* __restrict__ xlo)
{
    __shared__ float s[32 * KVSTR];
    const uint32_t sb = smem_u32(s);
    const int row0 = blockIdx.x * 32;
    const int tid  = threadIdx.x;

    // stage k|v via cp.async: 32 rows x 512 floats = 4096 granules, 16/thread
    #pragma unroll
    for (int i = 0; i < 16; i++) {
        int u = tid + 256 * i;
        int r = u >> 7, c4 = u & 127;
        cp_async16(sb + (uint32_t)(r * 129 + c4) * 16,
                   (const float4*)qkv + (size_t)(row0 + r) * 192 + 64 + c4);
    }
    cp_commit();

    const int r = tid >> 3;
    const int h = tid & 7;

    // q loads overlap with the cp.async bulk copy
    float q[32];
    {
        const float4* qsrc = (const float4*)(qkv + (size_t)(row0 + r) * 768 + h * 32);
        #pragma unroll
        for (int i = 0; i < 8; i++) {
            float4 f = qsrc[i];
            q[i * 4 + 0] = f.x; q[i * 4 + 1] = f.y;
            q[i * 4 + 2] = f.z; q[i * 4 + 3] = f.w;
        }
    }

    cp_wait<0>();
    __syncthreads();

    const float* k  = s + r * KVSTR;
    const float* vv = s + r * KVSTR + 256;

    const float scale = 0.17677669529663687f;  // 1/sqrt(32)

    float p[8];
    #pragma unroll
    for (int g = 0; g < 8; g++) p[g] = 0.0f;
    #pragma unroll
    for (int d = 0; d < 32; d++) {
        float qd = q[d];
        #pragma unroll
        for (int g = 0; g < 8; g++)
            p[g] = fmaf(qd, k[g * 32 + d], p[g]);
    }
    float mx = p[0] * scale;
    #pragma unroll
    for (int g = 1; g < 8; g++) mx = fmaxf(mx, p[g] * scale);
    float sum = 0.0f;
    #pragma unroll
    for (int g = 0; g < 8; g++) { p[g] = __expf(p[g] * scale - mx); sum += p[g]; }
    const float inv = 1.0f / sum;
    #pragma unroll
    for (int g = 0; g < 8; g++) p[g] *= inv;

    size_t base = (size_t)(row0 + r) * 256 + h * 32;
    #pragma unroll
    for (int cb = 0; cb < 4; cb++) {
        unsigned short hbuf[8], lbuf[8];
        #pragma unroll
        for (int dd = 0; dd < 8; dd++) {
            int d = cb * 8 + dd;
            float a = 0.0f;
            #pragma unroll
            for (int g = 0; g < 8; g++)
                a = fmaf(p[g], vv[g * 32 + d], a);
            __nv_bfloat16 hb = __float2bfloat16(a);
            __nv_bfloat16 lb = __float2bfloat16(a - __bfloat162float(hb));
            hbuf[dd] = *(unsigned short*)&hb;
            lbuf[dd] = *(unsigned short*)&lb;
        }
        *(uint4*)(xhi + base + cb * 8) = *(uint4*)hbuf;
        *(uint4*)(xlo + base + cb * 8) = *(uint4*)lbuf;
    }
}

// ---------------- launch ------------------------------------------------------
extern "C" void kernel_launch(void* const* d_in, const int* in_sizes, int n_in,
                              void* d_out, int out_size)
{
    const float* v  = (const float*)d_in[0];
    const float* Wq = (const float*)d_in[1];
    const float* Wk = (const float*)d_in[2];
    const float* Wv = (const float*)d_in[3];
    const float* Wp = (const float*)d_in[4];
    const float* bp = (const float*)d_in[5];
    float* out = (float*)d_out;

    unsigned short *xhi, *xlo, *wqkv, *wp;
    float *qkv;
    cudaGetSymbolAddress((void**)&xhi,  g_xhi);
    cudaGetSymbolAddress((void**)&xlo,  g_xlo);
    cudaGetSymbolAddress((void**)&wqkv, g_wqkv);
    cudaGetSymbolAddress((void**)&wp,   g_wp);
    cudaGetSymbolAddress((void**)&qkv,  g_qkv);

    cudaFuncSetAttribute(gemm3f_kernel, cudaFuncAttributeMaxDynamicSharedMemorySize, GEMM3F_SMEM);
    cudaFuncSetAttribute(gemm3_kernel,  cudaFuncAttributeMaxDynamicSharedMemorySize, GEMM_SMEM);

    wconv_kernel<<<dim3(256, 4), 256>>>(Wq, Wk, Wv, Wp, wqkv, wp);

    // merged QKV projection: N = 768, fp32 A converted in-kernel
    dim3 gq(6, M_TOTAL / 128);
    gemm3f_kernel<<<gq, 256, GEMM3F_SMEM>>>(v, wqkv, wqkv + 768 * 256, qkv, 768);

    // attention -> split x
    attn_kernel<<<M_TOTAL / 32, 256>>>(qkv, xhi, xlo);

    // output projection + bias
    dim3 gp(2, M_TOTAL / 128);
    gemm3_kernel<<<gp, 256, GEMM_SMEM>>>(xhi, xlo, wp, wp + 256 * 256, bp, out, DIM);
}

// round 8
// speedup vs baseline: 1.1151x; 1.1151x over previous
#include <cuda_runtime.h>
#include <cuda_bf16.h>
#include <cstdint>

// out = RowLocalAttn(v@Wq, v@Wk, v@Wv) @ Wp + bp
// v: [65536, 256] fp32. GEMMs: warp mma.sync bf16, 3-pass hi/lo split, fp32 accum.
// R8: R6 GEMM path restored (split_kernel + gemm3 3-stage); attention stages the
// full qkv row in smem via cp.async (fixes q L1-wavefront explosion); split+wconv
// merged into one launch.

#define M_TOTAL 65536
#define DIM     256

// ---------------- scratch ----------------------------------------------------
__device__ __align__(128) unsigned short g_vhi[(size_t)M_TOTAL * DIM];
__device__ __align__(128) unsigned short g_vlo[(size_t)M_TOTAL * DIM];
__device__ __align__(128) float          g_qkv[(size_t)M_TOTAL * 3 * DIM]; // [M][768]
__device__ __align__(128) unsigned short g_xhi[(size_t)M_TOTAL * DIM];
__device__ __align__(128) unsigned short g_xlo[(size_t)M_TOTAL * DIM];
__device__ __align__(128) unsigned short g_wqkv[2 * 768 * 256];  // hi plane, lo plane ([n][k])
__device__ __align__(128) unsigned short g_wp[2 * 256 * 256];

// ---------------- PTX helpers ------------------------------------------------
__device__ __forceinline__ uint32_t smem_u32(const void* p) {
    uint32_t a;
    asm("{ .reg .u64 t; cvta.to.shared.u64 t, %1; cvt.u32.u64 %0, t; }" : "=r"(a) : "l"(p));
    return a;
}
__device__ __forceinline__ void cp_async16(uint32_t s, const void* g) {
    asm volatile("cp.async.cg.shared.global [%0], [%1], 16;" :: "r"(s), "l"(g));
}
__device__ __forceinline__ void cp_commit() { asm volatile("cp.async.commit_group;"); }
template<int N>
__device__ __forceinline__ void cp_wait() { asm volatile("cp.async.wait_group %0;" :: "n"(N)); }
__device__ __forceinline__ void ldsm4(uint32_t* r, uint32_t a) {
    asm volatile("ldmatrix.sync.aligned.m8n8.x4.shared.b16 {%0,%1,%2,%3}, [%4];"
        : "=r"(r[0]), "=r"(r[1]), "=r"(r[2]), "=r"(r[3]) : "r"(a));
}
__device__ __forceinline__ void mma16816(float* d, const uint32_t* a, const uint32_t* b) {
    asm volatile("mma.sync.aligned.m16n8k16.row.col.f32.bf16.bf16.f32 "
        "{%0,%1,%2,%3}, {%4,%5,%6,%7}, {%8,%9}, {%0,%1,%2,%3};"
        : "+f"(d[0]), "+f"(d[1]), "+f"(d[2]), "+f"(d[3])
        : "r"(a[0]), "r"(a[1]), "r"(a[2]), "r"(a[3]), "r"(b[0]), "r"(b[1]));
}
// swizzled offset in an N-row x 64-byte tile (16B granules)
__device__ __forceinline__ uint32_t swz(int row, int c) {
    return (uint32_t)(row * 64 + ((c ^ ((row >> 1) & 3)) << 4));
}

// ---------------- fused split + weight conversion ----------------------------
// blocks [0, 16384): split v into hi/lo bf16 planes (256 thr, 1 float4 each)
// blocks [16384, 17408): weight transpose+split (1024 blocks)
__global__ __launch_bounds__(256)
void prep_kernel(const float4* __restrict__ vin, uint2* __restrict__ vhi, uint2* __restrict__ vlo,
                 const float* __restrict__ Wq, const float* __restrict__ Wk,
                 const float* __restrict__ Wv, const float* __restrict__ Wp,
                 unsigned short* __restrict__ wqkv, unsigned short* __restrict__ wp)
{
    int bid = blockIdx.x;
    if (bid < 16384) {
        int i = bid * 256 + threadIdx.x;
        float4 f = vin[i];
        __nv_bfloat16 h0 = __float2bfloat16(f.x);
        __nv_bfloat16 h1 = __float2bfloat16(f.y);
        __nv_bfloat16 h2 = __float2bfloat16(f.z);
        __nv_bfloat16 h3 = __float2bfloat16(f.w);
        __nv_bfloat16 l0 = __float2bfloat16(f.x - __bfloat162float(h0));
        __nv_bfloat16 l1 = __float2bfloat16(f.y - __bfloat162float(h1));
        __nv_bfloat16 l2 = __float2bfloat16(f.z - __bfloat162float(h2));
        __nv_bfloat16 l3 = __float2bfloat16(f.w - __bfloat162float(h3));
        __nv_bfloat162 hp0 = __nv_bfloat162(h0, h1), hp1 = __nv_bfloat162(h2, h3);
        __nv_bfloat162 lp0 = __nv_bfloat162(l0, l1), lp1 = __nv_bfloat162(l2, l3);
        uint2 ho, lo2;
        ho.x = *(uint32_t*)&hp0; ho.y = *(uint32_t*)&hp1;
        lo2.x = *(uint32_t*)&lp0; lo2.y = *(uint32_t*)&lp1;
        vhi[i] = ho; vlo[i] = lo2;
    } else {
        int idx = bid - 16384;
        int wi = idx >> 8;
        int n  = idx & 255;
        int k  = threadIdx.x;
        const float* W = (wi == 0) ? Wq : (wi == 1) ? Wk : (wi == 2) ? Wv : Wp;
        float val = W[k * 256 + n];
        __nv_bfloat16 h = __float2bfloat16(val);
        __nv_bfloat16 l = __float2bfloat16(val - __bfloat162float(h));
        if (wi < 3) {
            wqkv[(size_t)(wi * 256 + n) * 256 + k]                     = *(unsigned short*)&h;
            wqkv[(size_t)768 * 256 + (size_t)(wi * 256 + n) * 256 + k] = *(unsigned short*)&l;
        } else {
            wp[(size_t)n * 256 + k]                     = *(unsigned short*)&h;
            wp[(size_t)256 * 256 + (size_t)n * 256 + k] = *(unsigned short*)&l;
        }
    }
}

// ---------------- split-bf16 GEMM, 3-stage pipeline, pass-reordered MMAs -----
static constexpr int STAGE_BYTES = 32768;
static constexpr int OFF_AH = 0, OFF_AL = 8192, OFF_BH = 16384, OFF_BL = 24576;
static constexpr int GEMM_SMEM = 3 * STAGE_BYTES;

template<bool BIAS>
__global__ __launch_bounds__(256)
void gemm3_kernel(const unsigned short* __restrict__ Ahi, const unsigned short* __restrict__ Alo,
                  const unsigned short* __restrict__ Bhi, const unsigned short* __restrict__ Blo,
                  const float* __restrict__ bias, float* __restrict__ C, int ldc)
{
    extern __shared__ char smem[];
    const uint32_t sb = smem_u32(smem);
    const int tid  = threadIdx.x;
    const int wid  = tid >> 5;
    const int lane = tid & 31;
    const int mw = wid & 1;        // 2 warp rows (64 each)
    const int nw = wid >> 1;       // 4 warp cols (32 each)

    const int mbase = blockIdx.y * 128;
    const int nbase = blockIdx.x * 128;

    auto load_chunk = [&](int kc, int s) {
        const uint32_t stg = sb + s * STAGE_BYTES;
        #pragma unroll
        for (int i = 0; i < 2; i++) {
            int u = tid + i * 256;             // 512 16B-units per 8K tile
            int row = u >> 2, c = u & 3;
            uint32_t so = swz(row, c);
            size_t ga = (size_t)(mbase + row) * 256 + kc * 32 + c * 8;
            size_t gb = (size_t)(nbase + row) * 256 + kc * 32 + c * 8;
            cp_async16(stg + OFF_AH + so, Ahi + ga);
            cp_async16(stg + OFF_AL + so, Alo + ga);
            cp_async16(stg + OFF_BH + so, Bhi + gb);
            cp_async16(stg + OFF_BL + so, Blo + gb);
        }
        cp_commit();
    };

    float acc[4][4][4];
    #pragma unroll
    for (int i = 0; i < 4; i++)
        #pragma unroll
        for (int j = 0; j < 4; j++)
            #pragma unroll
            for (int r = 0; r < 4; r++) acc[i][j][r] = 0.0f;

    load_chunk(0, 0);
    load_chunk(1, 1);

    for (int kc = 0; kc < 8; kc++) {
        if (kc == 7) cp_wait<0>(); else cp_wait<1>();
        __syncthreads();
        if (kc < 6) load_chunk(kc + 2, (kc + 2) % 3);

        const uint32_t stg = sb + (kc % 3) * STAGE_BYTES;
        #pragma unroll
        for (int ks = 0; ks < 2; ks++) {
            uint32_t a_hi[4][4], a_lo[4][4];
            {
                int ar = mw * 64 + (lane & 15);
                int ac = ks * 2 + (lane >> 4);
                uint32_t base_off = swz(ar, ac);
                #pragma unroll
                for (int mt = 0; mt < 4; mt++) {
                    uint32_t off = base_off + mt * 16 * 64;
                    ldsm4(a_hi[mt], stg + OFF_AH + off);
                    ldsm4(a_lo[mt], stg + OFF_AL + off);
                }
            }
            uint32_t b_hi[4][2], b_lo[4][2];
            {
                int nr0 = nw * 32 + ((lane >> 4) << 3) + (lane & 7);
                int bc  = ks * 2 + ((lane >> 3) & 1);
                #pragma unroll
                for (int nh = 0; nh < 2; nh++) {
                    uint32_t off = swz(nr0 + nh * 16, bc);
                    uint32_t r[4];
                    ldsm4(r, stg + OFF_BH + off);
                    b_hi[nh * 2][0] = r[0]; b_hi[nh * 2][1] = r[1];
                    b_hi[nh * 2 + 1][0] = r[2]; b_hi[nh * 2 + 1][1] = r[3];
                    ldsm4(r, stg + OFF_BL + off);
                    b_lo[nh * 2][0] = r[0]; b_lo[nh * 2][1] = r[1];
                    b_lo[nh * 2 + 1][0] = r[2]; b_lo[nh * 2 + 1][1] = r[3];
                }
            }
            // pass-outermost: consecutive MMAs hit different accumulators
            #pragma unroll
            for (int mt = 0; mt < 4; mt++)
                #pragma unroll
                for (int nt = 0; nt < 4; nt++)
                    mma16816(acc[mt][nt], a_hi[mt], b_hi[nt]);
            #pragma unroll
            for (int mt = 0; mt < 4; mt++)
                #pragma unroll
                for (int nt = 0; nt < 4; nt++)
                    mma16816(acc[mt][nt], a_hi[mt], b_lo[nt]);
            #pragma unroll
            for (int mt = 0; mt < 4; mt++)
                #pragma unroll
                for (int nt = 0; nt < 4; nt++)
                    mma16816(acc[mt][nt], a_lo[mt], b_hi[nt]);
        }
    }

    #pragma unroll
    for (int mt = 0; mt < 4; mt++) {
        int r0 = mbase + mw * 64 + mt * 16 + (lane >> 2);
        #pragma unroll
        for (int nt = 0; nt < 4; nt++) {
            int col = nbase + nw * 32 + nt * 8 + (lane & 3) * 2;
            float b0 = 0.f, b1 = 0.f;
            if (BIAS) { b0 = bias[col]; b1 = bias[col + 1]; }
            *(float2*)(C + (size_t)r0 * ldc + col) =
                make_float2(acc[mt][nt][0] + b0, acc[mt][nt][1] + b1);
            *(float2*)(C + (size_t)(r0 + 8) * ldc + col) =
                make_float2(acc[mt][nt][2] + b0, acc[mt][nt][3] + b1);
        }
    }
}

// ---------------- row-local attention ----------------------------------------
// 32 rows/CTA, 256 threads = (row r = tid/8, head h = tid%8).
// Full qkv row (768 floats) staged in smem via cp.async, stride 772:
//   q read via LDS.128 (crossbar-floor), k/v broadcast across heads.
// All register arrays statically indexed.
#define ROWSTR 772
static constexpr int ATTN_SMEM = 32 * ROWSTR * 4;   // 98816 B

__global__ __launch_bounds__(256, 2)
void attn_kernel(const float* __restrict__ qkv,
                 unsigned short* __restrict__ xhi, unsigned short* __restrict__ xlo)
{
    extern __shared__ float s[];
    const uint32_t sb = smem_u32(s);
    const int row0 = blockIdx.x * 32;
    const int tid  = threadIdx.x;

    // stage 32 rows x 768 floats = 6144 granules, 24 per thread
    #pragma unroll
    for (int i = 0; i < 24; i++) {
        int u = tid + 256 * i;
        int r = u / 192, c4 = u % 192;
        cp_async16(sb + (uint32_t)(r * 193 + c4) * 16,
                   (const float4*)qkv + (size_t)(row0 + r) * 192 + c4);
    }
    cp_commit();
    cp_wait<0>();
    __syncthreads();

    const int r = tid >> 3;
    const int h = tid & 7;
    const float* qs = s + r * ROWSTR + h * 32;
    const float* k  = s + r * ROWSTR + 256;
    const float* vv = s + r * ROWSTR + 512;

    // q into registers (8 x LDS.128; 4-phase crossbar floor)
    float q[32];
    #pragma unroll
    for (int i = 0; i < 8; i++) {
        float4 f = *(const float4*)(qs + i * 4);
        q[i * 4 + 0] = f.x; q[i * 4 + 1] = f.y;
        q[i * 4 + 2] = f.z; q[i * 4 + 3] = f.w;
    }

    const float scale = 0.17677669529663687f;  // 1/sqrt(32)

    float p[8];
    #pragma unroll
    for (int g = 0; g < 8; g++) p[g] = 0.0f;
    #pragma unroll
    for (int d = 0; d < 32; d++) {
        float qd = q[d];
        #pragma unroll
        for (int g = 0; g < 8; g++)
            p[g] = fmaf(qd, k[g * 32 + d], p[g]);
    }
    float mx = p[0] * scale;
    #pragma unroll
    for (int g = 1; g < 8; g++) mx = fmaxf(mx, p[g] * scale);
    float sum = 0.0f;
    #pragma unroll
    for (int g = 0; g < 8; g++) { p[g] = __expf(p[g] * scale - mx); sum += p[g]; }
    const float inv = 1.0f / sum;
    #pragma unroll
    for (int g = 0; g < 8; g++) p[g] *= inv;

    size_t base = (size_t)(row0 + r) * 256 + h * 32;
    #pragma unroll
    for (int cb = 0; cb < 4; cb++) {
        unsigned short hbuf[8], lbuf[8];
        #pragma unroll
        for (int dd = 0; dd < 8; dd++) {
            int d = cb * 8 + dd;
            float a = 0.0f;
            #pragma unroll
            for (int g = 0; g < 8; g++)
                a = fmaf(p[g], vv[g * 32 + d], a);
            __nv_bfloat16 hb = __float2bfloat16(a);
            __nv_bfloat16 lb = __float2bfloat16(a - __bfloat162float(hb));
            hbuf[dd] = *(unsigned short*)&hb;
            lbuf[dd] = *(unsigned short*)&lb;
        }
        *(uint4*)(xhi + base + cb * 8) = *(uint4*)hbuf;
        *(uint4*)(xlo + base + cb * 8) = *(uint4*)lbuf;
    }
}

// ---------------- launch ------------------------------------------------------
extern "C" void kernel_launch(void* const* d_in, const int* in_sizes, int n_in,
                              void* d_out, int out_size)
{
    const float* v  = (const float*)d_in[0];
    const float* Wq = (const float*)d_in[1];
    const float* Wk = (const float*)d_in[2];
    const float* Wv = (const float*)d_in[3];
    const float* Wp = (const float*)d_in[4];
    const float* bp = (const float*)d_in[5];
    float* out = (float*)d_out;

    unsigned short *vhi, *vlo, *xhi, *xlo, *wqkv, *wp;
    float *qkv;
    cudaGetSymbolAddress((void**)&vhi,  g_vhi);
    cudaGetSymbolAddress((void**)&vlo,  g_vlo);
    cudaGetSymbolAddress((void**)&xhi,  g_xhi);
    cudaGetSymbolAddress((void**)&xlo,  g_xlo);
    cudaGetSymbolAddress((void**)&wqkv, g_wqkv);
    cudaGetSymbolAddress((void**)&wp,   g_wp);
    cudaGetSymbolAddress((void**)&qkv,  g_qkv);

    cudaFuncSetAttribute(gemm3_kernel<false>, cudaFuncAttributeMaxDynamicSharedMemorySize, GEMM_SMEM);
    cudaFuncSetAttribute(gemm3_kernel<true>,  cudaFuncAttributeMaxDynamicSharedMemorySize, GEMM_SMEM);
    cudaFuncSetAttribute(attn_kernel, cudaFuncAttributeMaxDynamicSharedMemorySize, ATTN_SMEM);

    // fused split + weight conversion
    prep_kernel<<<16384 + 1024, 256>>>((const float4*)v, (uint2*)vhi, (uint2*)vlo,
                                       Wq, Wk, Wv, Wp, wqkv, wp);

    // merged QKV projection: N = 768
    dim3 gq(6, M_TOTAL / 128);
    gemm3_kernel<false><<<gq, 256, GEMM_SMEM>>>(vhi, vlo, wqkv, wqkv + 768 * 256,
                                                nullptr, qkv, 768);
    // attention -> split x
    attn_kernel<<<M_TOTAL / 32, 256, ATTN_SMEM>>>(qkv, xhi, xlo);

    // output projection + bias
    dim3 gp(2, M_TOTAL / 128);
    gemm3_kernel<true><<<gp, 256, GEMM_SMEM>>>(xhi, xlo, wp, wp + 256 * 256,
                                               bp, out, DIM);
}

// round 9
// speedup vs baseline: 1.9120x; 1.7147x over previous
#include <cuda_runtime.h>
#include <cuda_fp16.h>
#include <cstdint>

// out = RowLocalAttn(v@Wq, v@Wk, v@Wv) @ Wp + bp
// v: [65536, 256] fp32. R9: single-pass fp16 mma.sync GEMMs (fp32 accum).
// fp16's 11-bit mantissa gives ~3-5e-4 end-to-end rel err (threshold 1e-3),
// for 3x less tensor work than the R8 split-bf16 3-pass scheme.

#define M_TOTAL 65536
#define DIM     256

// ---------------- scratch ----------------------------------------------------
__device__ __align__(128) unsigned short g_vh[(size_t)M_TOTAL * DIM];      // fp16 v
__device__ __align__(128) float          g_qkv[(size_t)M_TOTAL * 3 * DIM]; // [M][768] fp32
__device__ __align__(128) unsigned short g_xh[(size_t)M_TOTAL * DIM];      // fp16 x
__device__ __align__(128) unsigned short g_wqkv[768 * 256];                // fp16 [n][k]
__device__ __align__(128) unsigned short g_wp[256 * 256];                  // fp16 [n][k]

// ---------------- PTX helpers ------------------------------------------------
__device__ __forceinline__ uint32_t smem_u32(const void* p) {
    uint32_t a;
    asm("{ .reg .u64 t; cvta.to.shared.u64 t, %1; cvt.u32.u64 %0, t; }" : "=r"(a) : "l"(p));
    return a;
}
__device__ __forceinline__ void cp_async16(uint32_t s, const void* g) {
    asm volatile("cp.async.cg.shared.global [%0], [%1], 16;" :: "r"(s), "l"(g));
}
__device__ __forceinline__ void cp_commit() { asm volatile("cp.async.commit_group;"); }
template<int N>
__device__ __forceinline__ void cp_wait() { asm volatile("cp.async.wait_group %0;" :: "n"(N)); }
__device__ __forceinline__ void ldsm4(uint32_t* r, uint32_t a) {
    asm volatile("ldmatrix.sync.aligned.m8n8.x4.shared.b16 {%0,%1,%2,%3}, [%4];"
        : "=r"(r[0]), "=r"(r[1]), "=r"(r[2]), "=r"(r[3]) : "r"(a));
}
__device__ __forceinline__ void mma16816(float* d, const uint32_t* a, const uint32_t* b) {
    asm volatile("mma.sync.aligned.m16n8k16.row.col.f32.f16.f16.f32 "
        "{%0,%1,%2,%3}, {%4,%5,%6,%7}, {%8,%9}, {%0,%1,%2,%3};"
        : "+f"(d[0]), "+f"(d[1]), "+f"(d[2]), "+f"(d[3])
        : "r"(a[0]), "r"(a[1]), "r"(a[2]), "r"(a[3]), "r"(b[0]), "r"(b[1]));
}
// swizzled offset in an N-row x 64-byte tile (16B granules)
__device__ __forceinline__ uint32_t swz(int row, int c) {
    return (uint32_t)(row * 64 + ((c ^ ((row >> 1) & 3)) << 4));
}

// ---------------- fused v-convert + weight conversion ------------------------
// blocks [0, 16384): v fp32 -> fp16 (256 thr x 1 float4 each)
// blocks [16384, 17408): weight transpose+convert
__global__ __launch_bounds__(256)
void prep_kernel(const float4* __restrict__ vin, uint2* __restrict__ vh,
                 const float* __restrict__ Wq, const float* __restrict__ Wk,
                 const float* __restrict__ Wv, const float* __restrict__ Wp,
                 unsigned short* __restrict__ wqkv, unsigned short* __restrict__ wp)
{
    int bid = blockIdx.x;
    if (bid < 16384) {
        int i = bid * 256 + threadIdx.x;
        float4 f = vin[i];
        __half2 p0 = __floats2half2_rn(f.x, f.y);
        __half2 p1 = __floats2half2_rn(f.z, f.w);
        uint2 o;
        o.x = *(uint32_t*)&p0;
        o.y = *(uint32_t*)&p1;
        vh[i] = o;
    } else {
        int idx = bid - 16384;
        int wi = idx >> 8;
        int n  = idx & 255;
        int k  = threadIdx.x;
        const float* W = (wi == 0) ? Wq : (wi == 1) ? Wk : (wi == 2) ? Wv : Wp;
        __half h = __float2half_rn(W[k * 256 + n]);
        if (wi < 3)
            wqkv[(size_t)(wi * 256 + n) * 256 + k] = *(unsigned short*)&h;
        else
            wp[(size_t)n * 256 + k] = *(unsigned short*)&h;
    }
}

// ---------------- single-pass fp16 GEMM, 3-stage cp.async pipeline -----------
// C[by*128..+128][bx*128..+128] = A @ B^T (+bias). A fp16 [M][256], B fp16 [Ntot][256].
static constexpr int STAGE_BYTES = 16384;          // A 8K | B 8K
static constexpr int OFF_A = 0, OFF_B = 8192;
static constexpr int GEMM_SMEM = 3 * STAGE_BYTES;  // 49152

template<bool BIAS>
__global__ __launch_bounds__(256)
void gemm_kernel(const unsigned short* __restrict__ A,
                 const unsigned short* __restrict__ B,
                 const float* __restrict__ bias, float* __restrict__ C, int ldc)
{
    extern __shared__ char smem[];
    const uint32_t sb = smem_u32(smem);
    const int tid  = threadIdx.x;
    const int wid  = tid >> 5;
    const int lane = tid & 31;
    const int mw = wid & 1;        // 2 warp rows (64 each)
    const int nw = wid >> 1;       // 4 warp cols (32 each)

    const int mbase = blockIdx.y * 128;
    const int nbase = blockIdx.x * 128;

    auto load_chunk = [&](int kc, int s) {
        const uint32_t stg = sb + s * STAGE_BYTES;
        #pragma unroll
        for (int i = 0; i < 2; i++) {
            int u = tid + i * 256;             // 512 16B-units per 8K tile
            int row = u >> 2, c = u & 3;
            uint32_t so = swz(row, c);
            size_t ga = (size_t)(mbase + row) * 256 + kc * 32 + c * 8;
            size_t gb = (size_t)(nbase + row) * 256 + kc * 32 + c * 8;
            cp_async16(stg + OFF_A + so, A + ga);
            cp_async16(stg + OFF_B + so, B + gb);
        }
        cp_commit();
    };

    float acc[4][4][4];
    #pragma unroll
    for (int i = 0; i < 4; i++)
        #pragma unroll
        for (int j = 0; j < 4; j++)
            #pragma unroll
            for (int r = 0; r < 4; r++) acc[i][j][r] = 0.0f;

    load_chunk(0, 0);
    load_chunk(1, 1);

    for (int kc = 0; kc < 8; kc++) {
        if (kc == 7) cp_wait<0>(); else cp_wait<1>();
        __syncthreads();
        if (kc < 6) load_chunk(kc + 2, (kc + 2) % 3);

        const uint32_t stg = sb + (kc % 3) * STAGE_BYTES;
        #pragma unroll
        for (int ks = 0; ks < 2; ks++) {
            uint32_t a_f[4][4];
            {
                int ar = mw * 64 + (lane & 15);
                int ac = ks * 2 + (lane >> 4);
                uint32_t base_off = swz(ar, ac);
                #pragma unroll
                for (int mt = 0; mt < 4; mt++)
                    ldsm4(a_f[mt], stg + OFF_A + base_off + mt * 16 * 64);
            }
            uint32_t b_f[4][2];
            {
                int nr0 = nw * 32 + ((lane >> 4) << 3) + (lane & 7);
                int bc  = ks * 2 + ((lane >> 3) & 1);
                #pragma unroll
                for (int nh = 0; nh < 2; nh++) {
                    uint32_t off = swz(nr0 + nh * 16, bc);
                    uint32_t r[4];
                    ldsm4(r, stg + OFF_B + off);
                    b_f[nh * 2][0] = r[0]; b_f[nh * 2][1] = r[1];
                    b_f[nh * 2 + 1][0] = r[2]; b_f[nh * 2 + 1][1] = r[3];
                }
            }
            #pragma unroll
            for (int mt = 0; mt < 4; mt++)
                #pragma unroll
                for (int nt = 0; nt < 4; nt++)
                    mma16816(acc[mt][nt], a_f[mt], b_f[nt]);
        }
    }

    #pragma unroll
    for (int mt = 0; mt < 4; mt++) {
        int r0 = mbase + mw * 64 + mt * 16 + (lane >> 2);
        #pragma unroll
        for (int nt = 0; nt < 4; nt++) {
            int col = nbase + nw * 32 + nt * 8 + (lane & 3) * 2;
            float b0 = 0.f, b1 = 0.f;
            if (BIAS) { b0 = bias[col]; b1 = bias[col + 1]; }
            *(float2*)(C + (size_t)r0 * ldc + col) =
                make_float2(acc[mt][nt][0] + b0, acc[mt][nt][1] + b1);
            *(float2*)(C + (size_t)(r0 + 8) * ldc + col) =
                make_float2(acc[mt][nt][2] + b0, acc[mt][nt][3] + b1);
        }
    }
}

// ---------------- row-local attention ----------------------------------------
// 32 rows/CTA, 256 threads = (row r = tid/8, head h = tid%8).
// Full qkv row (768 fp32) staged in smem via cp.async, stride 772.
// Output x written as fp16.
#define ROWSTR 772
static constexpr int ATTN_SMEM = 32 * ROWSTR * 4;   // 98816 B

__global__ __launch_bounds__(256, 2)
void attn_kernel(const float* __restrict__ qkv, unsigned short* __restrict__ xh)
{
    extern __shared__ float s[];
    const uint32_t sb = smem_u32(s);
    const int row0 = blockIdx.x * 32;
    const int tid  = threadIdx.x;

    // stage 32 rows x 768 floats = 6144 granules, 24 per thread
    #pragma unroll
    for (int i = 0; i < 24; i++) {
        int u = tid + 256 * i;
        int r = u / 192, c4 = u % 192;
        cp_async16(sb + (uint32_t)(r * 193 + c4) * 16,
                   (const float4*)qkv + (size_t)(row0 + r) * 192 + c4);
    }
    cp_commit();
    cp_wait<0>();
    __syncthreads();

    const int r = tid >> 3;
    const int h = tid & 7;
    const float* qs = s + r * ROWSTR + h * 32;
    const float* k  = s + r * ROWSTR + 256;
    const float* vv = s + r * ROWSTR + 512;

    float q[32];
    #pragma unroll
    for (int i = 0; i < 8; i++) {
        float4 f = *(const float4*)(qs + i * 4);
        q[i * 4 + 0] = f.x; q[i * 4 + 1] = f.y;
        q[i * 4 + 2] = f.z; q[i * 4 + 3] = f.w;
    }

    const float scale = 0.17677669529663687f;  // 1/sqrt(32)

    float p[8];
    #pragma unroll
    for (int g = 0; g < 8; g++) p[g] = 0.0f;
    #pragma unroll
    for (int d = 0; d < 32; d++) {
        float qd = q[d];
        #pragma unroll
        for (int g = 0; g < 8; g++)
            p[g] = fmaf(qd, k[g * 32 + d], p[g]);
    }
    float mx = p[0] * scale;
    #pragma unroll
    for (int g = 1; g < 8; g++) mx = fmaxf(mx, p[g] * scale);
    float sum = 0.0f;
    #pragma unroll
    for (int g = 0; g < 8; g++) { p[g] = __expf(p[g] * scale - mx); sum += p[g]; }
    const float inv = 1.0f / sum;
    #pragma unroll
    for (int g = 0; g < 8; g++) p[g] *= inv;

    size_t base = (size_t)(row0 + r) * 256 + h * 32;
    #pragma unroll
    for (int cb = 0; cb < 4; cb++) {
        unsigned short hbuf[8];
        #pragma unroll
        for (int dd = 0; dd < 8; dd++) {
            int d = cb * 8 + dd;
            float a = 0.0f;
            #pragma unroll
            for (int g = 0; g < 8; g++)
                a = fmaf(p[g], vv[g * 32 + d], a);
            __half hh = __float2half_rn(a);
            hbuf[dd] = *(unsigned short*)&hh;
        }
        *(uint4*)(xh + base + cb * 8) = *(uint4*)hbuf;
    }
}

// ---------------- launch ------------------------------------------------------
extern "C" void kernel_launch(void* const* d_in, const int* in_sizes, int n_in,
                              void* d_out, int out_size)
{
    const float* v  = (const float*)d_in[0];
    const float* Wq = (const float*)d_in[1];
    const float* Wk = (const float*)d_in[2];
    const float* Wv = (const float*)d_in[3];
    const float* Wp = (const float*)d_in[4];
    const float* bp = (const float*)d_in[5];
    float* out = (float*)d_out;

    unsigned short *vh, *xh, *wqkv, *wp;
    float *qkv;
    cudaGetSymbolAddress((void**)&vh,   g_vh);
    cudaGetSymbolAddress((void**)&xh,   g_xh);
    cudaGetSymbolAddress((void**)&wqkv, g_wqkv);
    cudaGetSymbolAddress((void**)&wp,   g_wp);
    cudaGetSymbolAddress((void**)&qkv,  g_qkv);

    cudaFuncSetAttribute(gemm_kernel<false>, cudaFuncAttributeMaxDynamicSharedMemorySize, GEMM_SMEM);
    cudaFuncSetAttribute(gemm_kernel<true>,  cudaFuncAttributeMaxDynamicSharedMemorySize, GEMM_SMEM);
    cudaFuncSetAttribute(attn_kernel, cudaFuncAttributeMaxDynamicSharedMemorySize, ATTN_SMEM);

    // fused v-convert + weight conversion
    prep_kernel<<<16384 + 1024, 256>>>((const float4*)v, (uint2*)vh,
                                       Wq, Wk, Wv, Wp, wqkv, wp);

    // merged QKV projection: N = 768
    dim3 gq(6, M_TOTAL / 128);
    gemm_kernel<false><<<gq, 256, GEMM_SMEM>>>(vh, wqkv, nullptr, qkv, 768);

    // attention -> fp16 x
    attn_kernel<<<M_TOTAL / 32, 256, ATTN_SMEM>>>(qkv, xh);

    // output projection + bias
    dim3 gp(2, M_TOTAL / 128);
    gemm_kernel<true><<<gp, 256, GEMM_SMEM>>>(xh, wp, bp, out, DIM);
}

// round 10
// speedup vs baseline: 2.1368x; 1.1176x over previous
#include <cuda_runtime.h>
#include <cuda_fp16.h>
#include <cstdint>

// out = RowLocalAttn(v@Wq, v@Wk, v@Wv) @ Wp + bp
// v: [65536, 256] fp32. R10: single-pass fp16 mma.sync GEMMs (fp32 accum),
// qkv intermediate stored as fp16 (halves QKV-write + attn-read traffic).

#define M_TOTAL 65536
#define DIM     256

// ---------------- scratch ----------------------------------------------------
__device__ __align__(128) unsigned short g_vh[(size_t)M_TOTAL * DIM];       // fp16 v
__device__ __align__(128) unsigned short g_qkvh[(size_t)M_TOTAL * 3 * DIM]; // fp16 [M][768]
__device__ __align__(128) unsigned short g_xh[(size_t)M_TOTAL * DIM];       // fp16 x
__device__ __align__(128) unsigned short g_wqkv[768 * 256];                 // fp16 [n][k]
__device__ __align__(128) unsigned short g_wp[256 * 256];                   // fp16 [n][k]

// ---------------- PTX helpers ------------------------------------------------
__device__ __forceinline__ uint32_t smem_u32(const void* p) {
    uint32_t a;
    asm("{ .reg .u64 t; cvta.to.shared.u64 t, %1; cvt.u32.u64 %0, t; }" : "=r"(a) : "l"(p));
    return a;
}
__device__ __forceinline__ void cp_async16(uint32_t s, const void* g) {
    asm volatile("cp.async.cg.shared.global [%0], [%1], 16;" :: "r"(s), "l"(g));
}
__device__ __forceinline__ void cp_commit() { asm volatile("cp.async.commit_group;"); }
template<int N>
__device__ __forceinline__ void cp_wait() { asm volatile("cp.async.wait_group %0;" :: "n"(N)); }
__device__ __forceinline__ void ldsm4(uint32_t* r, uint32_t a) {
    asm volatile("ldmatrix.sync.aligned.m8n8.x4.shared.b16 {%0,%1,%2,%3}, [%4];"
        : "=r"(r[0]), "=r"(r[1]), "=r"(r[2]), "=r"(r[3]) : "r"(a));
}
__device__ __forceinline__ void mma16816(float* d, const uint32_t* a, const uint32_t* b) {
    asm volatile("mma.sync.aligned.m16n8k16.row.col.f32.f16.f16.f32 "
        "{%0,%1,%2,%3}, {%4,%5,%6,%7}, {%8,%9}, {%0,%1,%2,%3};"
        : "+f"(d[0]), "+f"(d[1]), "+f"(d[2]), "+f"(d[3])
        : "r"(a[0]), "r"(a[1]), "r"(a[2]), "r"(a[3]), "r"(b[0]), "r"(b[1]));
}
// swizzled offset in an N-row x 64-byte tile (16B granules)
__device__ __forceinline__ uint32_t swz(int row, int c) {
    return (uint32_t)(row * 64 + ((c ^ ((row >> 1) & 3)) << 4));
}

// ---------------- fused v-convert + weight conversion ------------------------
__global__ __launch_bounds__(256)
void prep_kernel(const float4* __restrict__ vin, uint2* __restrict__ vh,
                 const float* __restrict__ Wq, const float* __restrict__ Wk,
                 const float* __restrict__ Wv, const float* __restrict__ Wp,
                 unsigned short* __restrict__ wqkv, unsigned short* __restrict__ wp)
{
    int bid = blockIdx.x;
    if (bid < 16384) {
        int i = bid * 256 + threadIdx.x;
        float4 f = vin[i];
        __half2 p0 = __floats2half2_rn(f.x, f.y);
        __half2 p1 = __floats2half2_rn(f.z, f.w);
        uint2 o;
        o.x = *(uint32_t*)&p0;
        o.y = *(uint32_t*)&p1;
        vh[i] = o;
    } else {
        int idx = bid - 16384;
        int wi = idx >> 8;
        int n  = idx & 255;
        int k  = threadIdx.x;
        const float* W = (wi == 0) ? Wq : (wi == 1) ? Wk : (wi == 2) ? Wv : Wp;
        __half h = __float2half_rn(W[k * 256 + n]);
        if (wi < 3)
            wqkv[(size_t)(wi * 256 + n) * 256 + k] = *(unsigned short*)&h;
        else
            wp[(size_t)n * 256 + k] = *(unsigned short*)&h;
    }
}

// ---------------- single-pass fp16 GEMM, 3-stage cp.async pipeline -----------
// C[by*128..+128][bx*128..+128] = A @ B^T (+bias).
// HALF_OUT: C is fp16 (no bias); else fp32 (+bias).
static constexpr int STAGE_BYTES = 16384;          // A 8K | B 8K
static constexpr int OFF_A = 0, OFF_B = 8192;
static constexpr int GEMM_SMEM = 3 * STAGE_BYTES;  // 49152

template<bool HALF_OUT, bool BIAS>
__global__ __launch_bounds__(256)
void gemm_kernel(const unsigned short* __restrict__ A,
                 const unsigned short* __restrict__ B,
                 const float* __restrict__ bias, void* __restrict__ Cv, int ldc)
{
    extern __shared__ char smem[];
    const uint32_t sb = smem_u32(smem);
    const int tid  = threadIdx.x;
    const int wid  = tid >> 5;
    const int lane = tid & 31;
    const int mw = wid & 1;        // 2 warp rows (64 each)
    const int nw = wid >> 1;       // 4 warp cols (32 each)

    const int mbase = blockIdx.y * 128;
    const int nbase = blockIdx.x * 128;

    auto load_chunk = [&](int kc, int s) {
        const uint32_t stg = sb + s * STAGE_BYTES;
        #pragma unroll
        for (int i = 0; i < 2; i++) {
            int u = tid + i * 256;             // 512 16B-units per 8K tile
            int row = u >> 2, c = u & 3;
            uint32_t so = swz(row, c);
            size_t ga = (size_t)(mbase + row) * 256 + kc * 32 + c * 8;
            size_t gb = (size_t)(nbase + row) * 256 + kc * 32 + c * 8;
            cp_async16(stg + OFF_A + so, A + ga);
            cp_async16(stg + OFF_B + so, B + gb);
        }
        cp_commit();
    };

    float acc[4][4][4];
    #pragma unroll
    for (int i = 0; i < 4; i++)
        #pragma unroll
        for (int j = 0; j < 4; j++)
            #pragma unroll
            for (int r = 0; r < 4; r++) acc[i][j][r] = 0.0f;

    load_chunk(0, 0);
    load_chunk(1, 1);

    for (int kc = 0; kc < 8; kc++) {
        if (kc == 7) cp_wait<0>(); else cp_wait<1>();
        __syncthreads();
        if (kc < 6) load_chunk(kc + 2, (kc + 2) % 3);

        const uint32_t stg = sb + (kc % 3) * STAGE_BYTES;
        #pragma unroll
        for (int ks = 0; ks < 2; ks++) {
            uint32_t a_f[4][4];
            {
                int ar = mw * 64 + (lane & 15);
                int ac = ks * 2 + (lane >> 4);
                uint32_t base_off = swz(ar, ac);
                #pragma unroll
                for (int mt = 0; mt < 4; mt++)
                    ldsm4(a_f[mt], stg + OFF_A + base_off + mt * 16 * 64);
            }
            uint32_t b_f[4][2];
            {
                int nr0 = nw * 32 + ((lane >> 4) << 3) + (lane & 7);
                int bc  = ks * 2 + ((lane >> 3) & 1);
                #pragma unroll
                for (int nh = 0; nh < 2; nh++) {
                    uint32_t off = swz(nr0 + nh * 16, bc);
                    uint32_t r[4];
                    ldsm4(r, stg + OFF_B + off);
                    b_f[nh * 2][0] = r[0]; b_f[nh * 2][1] = r[1];
                    b_f[nh * 2 + 1][0] = r[2]; b_f[nh * 2 + 1][1] = r[3];
                }
            }
            #pragma unroll
            for (int mt = 0; mt < 4; mt++)
                #pragma unroll
                for (int nt = 0; nt < 4; nt++)
                    mma16816(acc[mt][nt], a_f[mt], b_f[nt]);
        }
    }

    if (HALF_OUT) {
        __half* C = (__half*)Cv;
        #pragma unroll
        for (int mt = 0; mt < 4; mt++) {
            int r0 = mbase + mw * 64 + mt * 16 + (lane >> 2);
            #pragma unroll
            for (int nt = 0; nt < 4; nt++) {
                int col = nbase + nw * 32 + nt * 8 + (lane & 3) * 2;
                __half2 h0 = __floats2half2_rn(acc[mt][nt][0], acc[mt][nt][1]);
                __half2 h1 = __floats2half2_rn(acc[mt][nt][2], acc[mt][nt][3]);
                *(uint32_t*)(C + (size_t)r0 * ldc + col)       = *(uint32_t*)&h0;
                *(uint32_t*)(C + (size_t)(r0 + 8) * ldc + col) = *(uint32_t*)&h1;
            }
        }
    } else {
        float* C = (float*)Cv;
        #pragma unroll
        for (int mt = 0; mt < 4; mt++) {
            int r0 = mbase + mw * 64 + mt * 16 + (lane >> 2);
            #pragma unroll
            for (int nt = 0; nt < 4; nt++) {
                int col = nbase + nw * 32 + nt * 8 + (lane & 3) * 2;
                float b0 = 0.f, b1 = 0.f;
                if (BIAS) { b0 = bias[col]; b1 = bias[col + 1]; }
                *(float2*)(C + (size_t)r0 * ldc + col) =
                    make_float2(acc[mt][nt][0] + b0, acc[mt][nt][1] + b1);
                *(float2*)(C + (size_t)(r0 + 8) * ldc + col) =
                    make_float2(acc[mt][nt][2] + b0, acc[mt][nt][3] + b1);
            }
        }
    }
}

// ---------------- row-local attention (fp16 qkv in, fp16 x out) --------------
// 32 rows/CTA, 256 threads = (row r = tid/8, head h = tid%8).
// Full qkv row (768 fp16 = 1536B) staged via cp.async, row stride 776 halves
// (1552B: rows land on distinct banks; k/v addresses broadcast across heads).
#define ROWH 776
static constexpr int ATTN_SMEM = 32 * ROWH * 2;   // 49664 B

__global__ __launch_bounds__(256, 4)
void attn_kernel(const __half* __restrict__ qkv, unsigned short* __restrict__ xh)
{
    extern __shared__ __half sh[];
    const uint32_t sb = smem_u32(sh);
    const int row0 = blockIdx.x * 32;
    const int tid  = threadIdx.x;

    // stage 32 rows x 96 granules (1536B/row), 12 per thread
    #pragma unroll
    for (int i = 0; i < 12; i++) {
        int u = tid + 256 * i;
        int r = u / 96, c = u % 96;
        cp_async16(sb + (uint32_t)(r * 97 + c) * 16,
                   (const uint4*)qkv + (size_t)(row0 + r) * 96 + c);
    }
    cp_commit();
    cp_wait<0>();
    __syncthreads();

    const int r = tid >> 3;
    const int h = tid & 7;
    const __half2* q2 = (const __half2*)(sh + r * ROWH + h * 32);
    const __half2* k2 = (const __half2*)(sh + r * ROWH + 256);
    const __half2* v2 = (const __half2*)(sh + r * ROWH + 512);

    float q[32];
    #pragma unroll
    for (int i = 0; i < 16; i++) {
        float2 f = __half22float2(q2[i]);
        q[2 * i] = f.x; q[2 * i + 1] = f.y;
    }

    const float scale = 0.17677669529663687f;  // 1/sqrt(32)

    float p[8];
    #pragma unroll
    for (int g = 0; g < 8; g++) p[g] = 0.0f;
    #pragma unroll
    for (int d2 = 0; d2 < 16; d2++) {
        float qx = q[2 * d2], qy = q[2 * d2 + 1];
        #pragma unroll
        for (int g = 0; g < 8; g++) {
            float2 kk = __half22float2(k2[g * 16 + d2]);
            p[g] = fmaf(qx, kk.x, fmaf(qy, kk.y, p[g]));
        }
    }
    float mx = p[0] * scale;
    #pragma unroll
    for (int g = 1; g < 8; g++) mx = fmaxf(mx, p[g] * scale);
    float sum = 0.0f;
    #pragma unroll
    for (int g = 0; g < 8; g++) { p[g] = __expf(p[g] * scale - mx); sum += p[g]; }
    const float inv = 1.0f / sum;
    #pragma unroll
    for (int g = 0; g < 8; g++) p[g] *= inv;

    size_t base = (size_t)(row0 + r) * 256 + h * 32;
    #pragma unroll
    for (int cb = 0; cb < 4; cb++) {
        uint32_t obuf[4];
        #pragma unroll
        for (int dd2 = 0; dd2 < 4; dd2++) {
            int d2 = cb * 4 + dd2;
            float ax = 0.0f, ay = 0.0f;
            #pragma unroll
            for (int g = 0; g < 8; g++) {
                float2 vvv = __half22float2(v2[g * 16 + d2]);
                ax = fmaf(p[g], vvv.x, ax);
                ay = fmaf(p[g], vvv.y, ay);
            }
            __half2 hh = __floats2half2_rn(ax, ay);
            obuf[dd2] = *(uint32_t*)&hh;
        }
        *(uint4*)(xh + base + cb * 8) = *(uint4*)obuf;
    }
}

// ---------------- launch ------------------------------------------------------
extern "C" void kernel_launch(void* const* d_in, const int* in_sizes, int n_in,
                              void* d_out, int out_size)
{
    const float* v  = (const float*)d_in[0];
    const float* Wq = (const float*)d_in[1];
    const float* Wk = (const float*)d_in[2];
    const float* Wv = (const float*)d_in[3];
    const float* Wp = (const float*)d_in[4];
    const float* bp = (const float*)d_in[5];
    float* out = (float*)d_out;

    unsigned short *vh, *xh, *wqkv, *wp, *qkvh;
    cudaGetSymbolAddress((void**)&vh,   g_vh);
    cudaGetSymbolAddress((void**)&xh,   g_xh);
    cudaGetSymbolAddress((void**)&wqkv, g_wqkv);
    cudaGetSymbolAddress((void**)&wp,   g_wp);
    cudaGetSymbolAddress((void**)&qkvh, g_qkvh);

    cudaFuncSetAttribute((const void*)gemm_kernel<true, false>,
                         cudaFuncAttributeMaxDynamicSharedMemorySize, GEMM_SMEM);
    cudaFuncSetAttribute((const void*)gemm_kernel<false, true>,
                         cudaFuncAttributeMaxDynamicSharedMemorySize, GEMM_SMEM);
    cudaFuncSetAttribute((const void*)attn_kernel,
                         cudaFuncAttributeMaxDynamicSharedMemorySize, ATTN_SMEM);

    // fused v-convert + weight conversion
    prep_kernel<<<16384 + 1024, 256>>>((const float4*)v, (uint2*)vh,
                                       Wq, Wk, Wv, Wp, wqkv, wp);

    // merged QKV projection: N = 768, fp16 output
    dim3 gq(6, M_TOTAL / 128);
    gemm_kernel<true, false><<<gq, 256, GEMM_SMEM>>>(vh, wqkv, nullptr, qkvh, 768);

    // attention: fp16 qkv -> fp16 x
    attn_kernel<<<M_TOTAL / 32, 256, ATTN_SMEM>>>((const __half*)qkvh, xh);

    // output projection + bias (fp32 out)
    dim3 gp(2, M_TOTAL / 128);
    gemm_kernel<false, true><<<gp, 256, GEMM_SMEM>>>(xh, wp, bp, out, DIM);
}

// round 11
// speedup vs baseline: 2.3029x; 1.0777x over previous
#include <cuda_runtime.h>
#include <cuda_fp16.h>
#include <cstdint>

// out = RowLocalAttn(v@Wq, v@Wk, v@Wv) @ Wp + bp
// v: [65536, 256] fp32. R11: fp16 mma.sync GEMMs with 64-wide K chunks
// (4 pipeline iterations instead of 8 -> half the sync bubbles), fp16 qkv.

#define M_TOTAL 65536
#define DIM     256

// ---------------- scratch ----------------------------------------------------
__device__ __align__(128) unsigned short g_vh[(size_t)M_TOTAL * DIM];       // fp16 v
__device__ __align__(128) unsigned short g_qkvh[(size_t)M_TOTAL * 3 * DIM]; // fp16 [M][768]
__device__ __align__(128) unsigned short g_xh[(size_t)M_TOTAL * DIM];       // fp16 x
__device__ __align__(128) unsigned short g_wqkv[768 * 256];                 // fp16 [n][k]
__device__ __align__(128) unsigned short g_wp[256 * 256];                   // fp16 [n][k]

// ---------------- PTX helpers ------------------------------------------------
__device__ __forceinline__ uint32_t smem_u32(const void* p) {
    uint32_t a;
    asm("{ .reg .u64 t; cvta.to.shared.u64 t, %1; cvt.u32.u64 %0, t; }" : "=r"(a) : "l"(p));
    return a;
}
__device__ __forceinline__ void cp_async16(uint32_t s, const void* g) {
    asm volatile("cp.async.cg.shared.global [%0], [%1], 16;" :: "r"(s), "l"(g));
}
__device__ __forceinline__ void cp_commit() { asm volatile("cp.async.commit_group;"); }
template<int N>
__device__ __forceinline__ void cp_wait() { asm volatile("cp.async.wait_group %0;" :: "n"(N)); }
__device__ __forceinline__ void ldsm4(uint32_t* r, uint32_t a) {
    asm volatile("ldmatrix.sync.aligned.m8n8.x4.shared.b16 {%0,%1,%2,%3}, [%4];"
        : "=r"(r[0]), "=r"(r[1]), "=r"(r[2]), "=r"(r[3]) : "r"(a));
}
__device__ __forceinline__ void mma16816(float* d, const uint32_t* a, const uint32_t* b) {
    asm volatile("mma.sync.aligned.m16n8k16.row.col.f32.f16.f16.f32 "
        "{%0,%1,%2,%3}, {%4,%5,%6,%7}, {%8,%9}, {%0,%1,%2,%3};"
        : "+f"(d[0]), "+f"(d[1]), "+f"(d[2]), "+f"(d[3])
        : "r"(a[0]), "r"(a[1]), "r"(a[2]), "r"(a[3]), "r"(b[0]), "r"(b[1]));
}
// swizzled offset in an N-row x 128-byte tile (16B granules, 8 per row)
__device__ __forceinline__ uint32_t swz8(int row, int c) {
    return (uint32_t)(row * 128 + ((c ^ (row & 7)) << 4));
}

// ---------------- fused v-convert + weight conversion ------------------------
__global__ __launch_bounds__(256)
void prep_kernel(const float4* __restrict__ vin, uint2* __restrict__ vh,
                 const float* __restrict__ Wq, const float* __restrict__ Wk,
                 const float* __restrict__ Wv, const float* __restrict__ Wp,
                 unsigned short* __restrict__ wqkv, unsigned short* __restrict__ wp)
{
    int bid = blockIdx.x;
    if (bid < 16384) {
        int i = bid * 256 + threadIdx.x;
        float4 f = vin[i];
        __half2 p0 = __floats2half2_rn(f.x, f.y);
        __half2 p1 = __floats2half2_rn(f.z, f.w);
        uint2 o;
        o.x = *(uint32_t*)&p0;
        o.y = *(uint32_t*)&p1;
        vh[i] = o;
    } else {
        int idx = bid - 16384;
        int wi = idx >> 8;
        int n  = idx & 255;
        int k  = threadIdx.x;
        const float* W = (wi == 0) ? Wq : (wi == 1) ? Wk : (wi == 2) ? Wv : Wp;
        __half h = __float2half_rn(W[k * 256 + n]);
        if (wi < 3)
            wqkv[(size_t)(wi * 256 + n) * 256 + k] = *(unsigned short*)&h;
        else
            wp[(size_t)n * 256 + k] = *(unsigned short*)&h;
    }
}

// ---------------- fp16 GEMM, 64-wide K chunks, 3-stage cp.async --------------
// C[by*128..+128][bx*128..+128] = A @ B^T (+bias).
// HALF_OUT: C fp16 (no bias); else fp32 (+bias).
static constexpr int STAGE_BYTES = 32768;          // A 16K | B 16K
static constexpr int OFF_A = 0, OFF_B = 16384;
static constexpr int GEMM_SMEM = 3 * STAGE_BYTES;  // 98304

template<bool HALF_OUT, bool BIAS>
__global__ __launch_bounds__(256)
void gemm_kernel(const unsigned short* __restrict__ A,
                 const unsigned short* __restrict__ B,
                 const float* __restrict__ bias, void* __restrict__ Cv, int ldc)
{
    extern __shared__ char smem[];
    const uint32_t sb = smem_u32(smem);
    const int tid  = threadIdx.x;
    const int wid  = tid >> 5;
    const int lane = tid & 31;
    const int mw = wid & 1;        // 2 warp rows (64 each)
    const int nw = wid >> 1;       // 4 warp cols (32 each)

    const int mbase = blockIdx.y * 128;
    const int nbase = blockIdx.x * 128;

    // one 64-wide K chunk: A 128x64 fp16 (16KB) + B 128x64 fp16 (16KB)
    auto load_chunk = [&](int kc, int s) {
        const uint32_t stg = sb + s * STAGE_BYTES;
        #pragma unroll
        for (int i = 0; i < 4; i++) {
            int u = tid + i * 256;             // 1024 granules per 16K tile
            int row = u >> 3, c = u & 7;
            uint32_t so = swz8(row, c);
            size_t ga = (size_t)(mbase + row) * 256 + kc * 64 + c * 8;
            size_t gb = (size_t)(nbase + row) * 256 + kc * 64 + c * 8;
            cp_async16(stg + OFF_A + so, A + ga);
            cp_async16(stg + OFF_B + so, B + gb);
        }
        cp_commit();
    };

    float acc[4][4][4];
    #pragma unroll
    for (int i = 0; i < 4; i++)
        #pragma unroll
        for (int j = 0; j < 4; j++)
            #pragma unroll
            for (int r = 0; r < 4; r++) acc[i][j][r] = 0.0f;

    load_chunk(0, 0);
    load_chunk(1, 1);

    for (int kc = 0; kc < 4; kc++) {
        if (kc == 3) cp_wait<0>(); else cp_wait<1>();
        __syncthreads();
        if (kc < 2) load_chunk(kc + 2, (kc + 2) % 3);

        const uint32_t stg = sb + (kc % 3) * STAGE_BYTES;
        #pragma unroll
        for (int ks = 0; ks < 4; ks++) {           // 4 k16 slices per chunk
            uint32_t a_f[4][4];
            {
                int ar = mw * 64 + (lane & 15);
                int ac = ks * 2 + (lane >> 4);
                #pragma unroll
                for (int mt = 0; mt < 4; mt++)
                    ldsm4(a_f[mt], stg + OFF_A + swz8(ar + mt * 16, ac));
            }
            uint32_t b_f[4][2];
            {
                int nr0 = nw * 32 + ((lane >> 4) << 3) + (lane & 7);
                int bc  = ks * 2 + ((lane >> 3) & 1);
                #pragma unroll
                for (int nh = 0; nh < 2; nh++) {
                    uint32_t r[4];
                    ldsm4(r, stg + OFF_B + swz8(nr0 + nh * 16, bc));
                    b_f[nh * 2][0] = r[0]; b_f[nh * 2][1] = r[1];
                    b_f[nh * 2 + 1][0] = r[2]; b_f[nh * 2 + 1][1] = r[3];
                }
            }
            #pragma unroll
            for (int mt = 0; mt < 4; mt++)
                #pragma unroll
                for (int nt = 0; nt < 4; nt++)
                    mma16816(acc[mt][nt], a_f[mt], b_f[nt]);
        }
    }

    if (HALF_OUT) {
        __half* C = (__half*)Cv;
        #pragma unroll
        for (int mt = 0; mt < 4; mt++) {
            int r0 = mbase + mw * 64 + mt * 16 + (lane >> 2);
            #pragma unroll
            for (int nt = 0; nt < 4; nt++) {
                int col = nbase + nw * 32 + nt * 8 + (lane & 3) * 2;
                __half2 h0 = __floats2half2_rn(acc[mt][nt][0], acc[mt][nt][1]);
                __half2 h1 = __floats2half2_rn(acc[mt][nt][2], acc[mt][nt][3]);
                *(uint32_t*)(C + (size_t)r0 * ldc + col)       = *(uint32_t*)&h0;
                *(uint32_t*)(C + (size_t)(r0 + 8) * ldc + col) = *(uint32_t*)&h1;
            }
        }
    } else {
        float* C = (float*)Cv;
        #pragma unroll
        for (int mt = 0; mt < 4; mt++) {
            int r0 = mbase + mw * 64 + mt * 16 + (lane >> 2);
            #pragma unroll
            for (int nt = 0; nt < 4; nt++) {
                int col = nbase + nw * 32 + nt * 8 + (lane & 3) * 2;
                float b0 = 0.f, b1 = 0.f;
                if (BIAS) { b0 = bias[col]; b1 = bias[col + 1]; }
                *(float2*)(C + (size_t)r0 * ldc + col) =
                    make_float2(acc[mt][nt][0] + b0, acc[mt][nt][1] + b1);
                *(float2*)(C + (size_t)(r0 + 8) * ldc + col) =
                    make_float2(acc[mt][nt][2] + b0, acc[mt][nt][3] + b1);
            }
        }
    }
}

// ---------------- row-local attention (fp16 qkv in, fp16 x out) --------------
// 32 rows/CTA, 256 threads = (row r = tid/8, head h = tid%8).
// Full qkv row (768 fp16 = 1536B) staged via cp.async, row stride 776 halves.
#define ROWH 776
static constexpr int ATTN_SMEM = 32 * ROWH * 2;   // 49664 B

__global__ __launch_bounds__(256, 4)
void attn_kernel(const __half* __restrict__ qkv, unsigned short* __restrict__ xh)
{
    extern __shared__ __half sh[];
    const uint32_t sb = smem_u32(sh);
    const int row0 = blockIdx.x * 32;
    const int tid  = threadIdx.x;

    // stage 32 rows x 96 granules (1536B/row), 12 per thread
    #pragma unroll
    for (int i = 0; i < 12; i++) {
        int u = tid + 256 * i;
        int r = u / 96, c = u % 96;
        cp_async16(sb + (uint32_t)(r * 97 + c) * 16,
                   (const uint4*)qkv + (size_t)(row0 + r) * 96 + c);
    }
    cp_commit();
    cp_wait<0>();
    __syncthreads();

    const int r = tid >> 3;
    const int h = tid & 7;
    const __half2* q2 = (const __half2*)(sh + r * ROWH + h * 32);
    const __half2* k2 = (const __half2*)(sh + r * ROWH + 256);
    const __half2* v2 = (const __half2*)(sh + r * ROWH + 512);

    float q[32];
    #pragma unroll
    for (int i = 0; i < 16; i++) {
        float2 f = __half22float2(q2[i]);
        q[2 * i] = f.x; q[2 * i + 1] = f.y;
    }

    const float scale = 0.17677669529663687f;  // 1/sqrt(32)

    float p[8];
    #pragma unroll
    for (int g = 0; g < 8; g++) p[g] = 0.0f;
    #pragma unroll
    for (int d2 = 0; d2 < 16; d2++) {
        float qx = q[2 * d2], qy = q[2 * d2 + 1];
        #pragma unroll
        for (int g = 0; g < 8; g++) {
            float2 kk = __half22float2(k2[g * 16 + d2]);
            p[g] = fmaf(qx, kk.x, fmaf(qy, kk.y, p[g]));
        }
    }
    float mx = p[0] * scale;
    #pragma unroll
    for (int g = 1; g < 8; g++) mx = fmaxf(mx, p[g] * scale);
    float sum = 0.0f;
    #pragma unroll
    for (int g = 0; g < 8; g++) { p[g] = __expf(p[g] * scale - mx); sum += p[g]; }
    const float inv = 1.0f / sum;
    #pragma unroll
    for (int g = 0; g < 8; g++) p[g] *= inv;

    size_t base = (size_t)(row0 + r) * 256 + h * 32;
    #pragma unroll
    for (int cb = 0; cb < 4; cb++) {
        uint32_t obuf[4];
        #pragma unroll
        for (int dd2 = 0; dd2 < 4; dd2++) {
            int d2 = cb * 4 + dd2;
            float ax = 0.0f, ay = 0.0f;
            #pragma unroll
            for (int g = 0; g < 8; g++) {
                float2 vvv = __half22float2(v2[g * 16 + d2]);
                ax = fmaf(p[g], vvv.x, ax);
                ay = fmaf(p[g], vvv.y, ay);
            }
            __half2 hh = __floats2half2_rn(ax, ay);
            obuf[dd2] = *(uint32_t*)&hh;
        }
        *(uint4*)(xh + base + cb * 8) = *(uint4*)obuf;
    }
}

// ---------------- launch ------------------------------------------------------
extern "C" void kernel_launch(void* const* d_in, const int* in_sizes, int n_in,
                              void* d_out, int out_size)
{
    const float* v  = (const float*)d_in[0];
    const float* Wq = (const float*)d_in[1];
    const float* Wk = (const float*)d_in[2];
    const float* Wv = (const float*)d_in[3];
    const float* Wp = (const float*)d_in[4];
    const float* bp = (const float*)d_in[5];
    float* out = (float*)d_out;

    unsigned short *vh, *xh, *wqkv, *wp, *qkvh;
    cudaGetSymbolAddress((void**)&vh,   g_vh);
    cudaGetSymbolAddress((void**)&xh,   g_xh);
    cudaGetSymbolAddress((void**)&wqkv, g_wqkv);
    cudaGetSymbolAddress((void**)&wp,   g_wp);
    cudaGetSymbolAddress((void**)&qkvh, g_qkvh);

    cudaFuncSetAttribute((const void*)gemm_kernel<true, false>,
                         cudaFuncAttributeMaxDynamicSharedMemorySize, GEMM_SMEM);
    cudaFuncSetAttribute((const void*)gemm_kernel<false, true>,
                         cudaFuncAttributeMaxDynamicSharedMemorySize, GEMM_SMEM);
    cudaFuncSetAttribute((const void*)attn_kernel,
                         cudaFuncAttributeMaxDynamicSharedMemorySize, ATTN_SMEM);

    // fused v-convert + weight conversion
    prep_kernel<<<16384 + 1024, 256>>>((const float4*)v, (uint2*)vh,
                                       Wq, Wk, Wv, Wp, wqkv, wp);

    // merged QKV projection: N = 768, fp16 output
    dim3 gq(6, M_TOTAL / 128);
    gemm_kernel<true, false><<<gq, 256, GEMM_SMEM>>>(vh, wqkv, nullptr, qkvh, 768);

    // attention: fp16 qkv -> fp16 x
    attn_kernel<<<M_TOTAL / 32, 256, ATTN_SMEM>>>((const __half*)qkvh, xh);

    // output projection + bias (fp32 out)
    dim3 gp(2, M_TOTAL / 128);
    gemm_kernel<false, true><<<gp, 256, GEMM_SMEM>>>(xh, wp, bp, out, DIM);
}